// round 12
// baseline (speedup 1.0000x reference)
#include <cuda_runtime.h>
#include <cuda_pipeline.h>
#include <cstdint>

#define BB 8192
#define TT 2048
#define NN 60
#define THREADS 256
#define BLOCKS 512
#define ROWS_PER_BLOCK (BB / BLOCKS)     // 16
#define DEPTH 4                           // smem pipeline stages (rows)
#define I4_ROW (TT / 4)                   // 512 int4 per row

// Math: mul is a group Cayley table, so the T-step scan
//   s_t = mul[x_t, s_{t-1}], s_0 = identity (0)
// collapses to the ordered product s = x_T * ... * x_1 (associativity only).
// The dataset's table is cyclic Z_60 (mul[a,b]=(a+b)%N): the ordered product
// is then (sum of x_t) % N — a pure memory-bound sum reduction. A 1-block
// pre-kernel verifies this once and publishes a flag.
//
// Perf lesson (R3/R4/R6/R8): ptxas repeatedly collapses register-resident
// load windows (regs=32 => MLP~4), starving DRAM. Fix: cp.async -> smem
// pipeline. MLP now lives in the LSU queue (4 stages x 8KB per block,
// ~110KB outstanding per SM), independent of register allocation. Each
// thread consumes only its own copied slots, so stage reuse needs no
// barriers; only the per-row block reduce syncs.

__device__ int g_cyclic;

__global__ void check_cyclic_kernel(const int* __restrict__ mul) {
    int ok = 1;
    for (int i = threadIdx.x; i < NN * NN; i += blockDim.x) {
        int a = i / NN;
        int b = i - a * NN;
        ok &= (mul[i] == (a + b) % NN);
    }
    ok = __syncthreads_and(ok);
    if (threadIdx.x == 0) g_cyclic = ok;
}

__global__ __launch_bounds__(THREADS)
void a5_scan_kernel(const float* __restrict__ scale_p,
                    const int*   __restrict__ ids,
                    const int*   __restrict__ mul,
                    float*       __restrict__ out) {
    __shared__ alignas(16) int4 buf[DEPTH][I4_ROW];   // 32 KB ring
    __shared__ int s_part[THREADS / 32];
    __shared__ int s_state;

    const int tid  = threadIdx.x;
    const int lane = tid & 31;
    const int wid  = tid >> 5;

    const float scale = __ldg(scale_p);
    const float hi = 10.0f * scale;
    const float lo = -10.0f * scale;

    if (g_cyclic) {
        const int row0 = blockIdx.x * ROWS_PER_BLOCK;
        const int4* base = reinterpret_cast<const int4*>(ids + (size_t)row0 * TT);

        // Prologue: fill DEPTH stages.
        #pragma unroll
        for (int r = 0; r < DEPTH; r++) {
            const int4* rp = base + (size_t)r * I4_ROW;
            __pipeline_memcpy_async(&buf[r][tid],           rp + tid,           16);
            __pipeline_memcpy_async(&buf[r][tid + THREADS], rp + tid + THREADS, 16);
            __pipeline_commit();
        }

        for (int r = 0; r < ROWS_PER_BLOCK; r++) {
            // Groups committed so far = DEPTH + r; allow DEPTH-1 pending
            // => groups 0..r complete (this thread's own copies).
            __pipeline_wait_prior(DEPTH - 1);
            const int st = r & (DEPTH - 1);

            int4 a = buf[st][tid];
            int4 b = buf[st][tid + THREADS];
            int sum = a.x + a.y + a.z + a.w + b.x + b.y + b.z + b.w;
            sum = __reduce_add_sync(0xffffffffu, sum);
            if (lane == 0) s_part[wid] = sum;
            __syncthreads();
            if (tid == 0) {
                int tot = 0;
                #pragma unroll
                for (int w = 0; w < THREADS / 32; w++) tot += s_part[w];
                s_state = tot % NN;
            }
            // Issue next row into the stage just freed (thread-private slots,
            // safe immediately after this thread's reads above).
            if (r + DEPTH < ROWS_PER_BLOCK) {
                const int4* rp = base + (size_t)(r + DEPTH) * I4_ROW;
                __pipeline_memcpy_async(&buf[st][tid],           rp + tid,           16);
                __pipeline_memcpy_async(&buf[st][tid + THREADS], rp + tid + THREADS, 16);
            }
            __pipeline_commit();   // always commit: keeps wait_prior exact in tail
            __syncthreads();

            const int s = s_state;
            if (tid < NN)
                out[(size_t)(row0 + r) * NN + tid] = (tid == s) ? hi : lo;
        }
    } else {
        // Generic ordered product over any group table (correctness path;
        // never taken on this dataset). Warp-per-row, 2 rows per warp.
        const int gwarp = blockIdx.x * (THREADS / 32) + wid;
        for (int rr = 0; rr < 2; rr++) {
            const int row = gwarp + rr * (BLOCKS * THREADS / 32);
            const int4* rp = reinterpret_cast<const int4*>(ids + (size_t)row * TT);
            int acc = -1;   // -1 = empty
            for (int i = 0; i < 16; i++) {
                // chunk c = i*32+lane covers times [4c,4c+4), t0<t1<t2<t3:
                // p = x3*x2*x1*x0 with a*b = mul[a][b]
                int4 c = __ldg(&rp[i * 32 + lane]);
                int a = __ldg(&mul[c.y * NN + c.x]);
                int b = __ldg(&mul[c.w * NN + c.z]);
                int x = __ldg(&mul[b * NN + a]);
                #pragma unroll
                for (int o = 1; o < 32; o <<= 1) {
                    int other = __shfl_xor_sync(0xffffffffu, x, o);
                    x = (lane & o) ? __ldg(&mul[x * NN + other])
                                   : __ldg(&mul[other * NN + x]);
                }
                acc = (acc < 0) ? x : __ldg(&mul[x * NN + acc]);
            }
            const int s = acc;
            float* op = out + (size_t)row * NN;
            op[lane] = (lane == s) ? hi : lo;
            if (lane < NN - 32)
                op[lane + 32] = (lane + 32 == s) ? hi : lo;
        }
    }
}

extern "C" void kernel_launch(void* const* d_in, const int* in_sizes, int n_in,
                              void* d_out, int out_size) {
    // Identify inputs by element count (robust to ordering):
    //   scale: 1 element, mul: 3600 elements, input_ids: B*T (largest)
    const float* scale = nullptr;
    const int*   ids   = nullptr;
    const int*   mul   = nullptr;
    for (int i = 0; i < n_in; i++) {
        if (in_sizes[i] == 1)               scale = (const float*)d_in[i];
        else if (in_sizes[i] == NN * NN)    mul   = (const int*)d_in[i];
        else                                ids   = (const int*)d_in[i];
    }
    check_cyclic_kernel<<<1, 1024>>>(mul);
    a5_scan_kernel<<<BLOCKS, THREADS>>>(scale, ids, mul, (float*)d_out);
}

// round 13
// speedup vs baseline: 1.0261x; 1.0261x over previous
#include <cuda_runtime.h>
#include <cuda_pipeline.h>
#include <cstdint>

#define BB 8192
#define TT 2048
#define NN 60
#define THREADS 256
#define BLOCKS 512
#define ROWS_PER_BLOCK (BB / BLOCKS)     // 16
#define DEPTH 4                           // smem pipeline stages (rows)
#define I4_ROW (TT / 4)                   // 512 int4 per row
#define NWARP (THREADS / 32)

// Math: mul is a group Cayley table, so the T-step scan
//   s_t = mul[x_t, s_{t-1}], s_0 = identity (0)
// collapses to the ordered product s = x_T * ... * x_1 (associativity only).
// The dataset's table is cyclic Z_60 (mul[a,b]=(a+b)%N): the ordered product
// is then (sum of x_t) % N — a pure memory-bound sum reduction.
//
// R13 structure: SINGLE kernel. The cyclic-structure check (previously a
// serialized 1-block pre-kernel, 1-3us of critical path per replay) is now
// done per-block, overlapped under the cp.async prologue's DRAM latency
// (table is L2-hot after the first wave). Steady loop has ONE barrier per
// row: per-warp REDUX partials -> parity-double-buffered s_part -> barrier
// -> warps 0-1 finish the sum and store, warps 2-7 immediately issue the
// next stage. Stage reuse needs no barrier (thread-private slots, reads
// retire before re-issue).

__global__ __launch_bounds__(THREADS)
void a5_scan_kernel(const float* __restrict__ scale_p,
                    const int*   __restrict__ ids,
                    const int*   __restrict__ mul,
                    float*       __restrict__ out) {
    __shared__ alignas(16) int4 buf[DEPTH][I4_ROW];   // 32 KB ring
    __shared__ int s_part[2][NWARP];                  // parity double-buffer

    const int tid  = threadIdx.x;
    const int lane = tid & 31;
    const int wid  = tid >> 5;

    const int row0 = blockIdx.x * ROWS_PER_BLOCK;
    const int4* base = reinterpret_cast<const int4*>(ids + (size_t)row0 * TT);

    // 1) Prologue: fill DEPTH stages (one commit group per row per thread).
    #pragma unroll
    for (int r = 0; r < DEPTH; r++) {
        const int4* rp = base + (size_t)r * I4_ROW;
        __pipeline_memcpy_async(&buf[r][tid],           rp + tid,           16);
        __pipeline_memcpy_async(&buf[r][tid + THREADS], rp + tid + THREADS, 16);
        __pipeline_commit();
    }

    // 2) Table check, overlapped under the in-flight cp.asyncs.
    int ok = 1;
    for (int i = tid; i < NN * NN; i += THREADS) {
        int a = i / NN;
        int b = i - a * NN;
        ok &= (__ldg(&mul[i]) == (a + b) % NN);
    }
    const bool cyclic = (__syncthreads_and(ok) != 0);

    const float scale = __ldg(scale_p);
    const float hi = 10.0f * scale;
    const float lo = -10.0f * scale;

    if (cyclic) {
        for (int r = 0; r < ROWS_PER_BLOCK; r++) {
            // Committed so far = DEPTH + r; allow DEPTH-1 pending
            // => groups 0..r complete (this thread's own copies).
            __pipeline_wait_prior(DEPTH - 1);
            const int st = r & (DEPTH - 1);

            int4 a = buf[st][tid];
            int4 b = buf[st][tid + THREADS];
            int sum = a.x + a.y + a.z + a.w + b.x + b.y + b.z + b.w;
            sum = __reduce_add_sync(0xffffffffu, sum);
            if (lane == 0) s_part[r & 1][wid] = sum;
            __syncthreads();   // the ONLY barrier per row

            // Warps 2..7: issue next row into the freed stage right away.
            // (Reads of buf[st] above retired before the barrier; slots are
            // thread-private, so no further sync needed.)
            if (r + DEPTH < ROWS_PER_BLOCK) {
                const int4* rp = base + (size_t)(r + DEPTH) * I4_ROW;
                __pipeline_memcpy_async(&buf[st][tid],           rp + tid,           16);
                __pipeline_memcpy_async(&buf[st][tid + THREADS], rp + tid + THREADS, 16);
            }
            __pipeline_commit();   // commit every row: keeps wait_prior exact

            // Warps 0-1 (60 threads) finish the reduce redundantly + store.
            if (wid < 2) {
                int tot = 0;
                #pragma unroll
                for (int w = 0; w < NWARP; w++) tot += s_part[r & 1][w];
                const int s = tot % NN;
                const int col = wid * 32 + lane;
                if (col < NN)
                    out[(size_t)(row0 + r) * NN + col] = (col == s) ? hi : lo;
            }
            // s_part reuse is safe: next row uses the other parity slot, and
            // no warp can be >1 row ahead (barrier per row).
        }
    } else {
        // Generic ordered product over any group table (correctness path;
        // never taken on this dataset). Drain pipeline, then warp-per-row.
        __pipeline_wait_prior(0);
        const int gwarp = blockIdx.x * NWARP + wid;
        for (int rr = 0; rr < 2; rr++) {
            const int row = gwarp + rr * (BLOCKS * NWARP);
            const int4* rp = reinterpret_cast<const int4*>(ids + (size_t)row * TT);
            int acc = -1;   // -1 = empty
            for (int i = 0; i < 16; i++) {
                // chunk c = i*32+lane covers times [4c,4c+4), t0<t1<t2<t3:
                // p = x3*x2*x1*x0 with a*b = mul[a][b]
                int4 c = __ldg(&rp[i * 32 + lane]);
                int a = __ldg(&mul[c.y * NN + c.x]);
                int b = __ldg(&mul[c.w * NN + c.z]);
                int x = __ldg(&mul[b * NN + a]);
                #pragma unroll
                for (int o = 1; o < 32; o <<= 1) {
                    int other = __shfl_xor_sync(0xffffffffu, x, o);
                    x = (lane & o) ? __ldg(&mul[x * NN + other])
                                   : __ldg(&mul[other * NN + x]);
                }
                acc = (acc < 0) ? x : __ldg(&mul[x * NN + acc]);
            }
            const int s = acc;
            float* op = out + (size_t)row * NN;
            op[lane] = (lane == s) ? hi : lo;
            if (lane < NN - 32)
                op[lane + 32] = (lane + 32 == s) ? hi : lo;
        }
    }
}

extern "C" void kernel_launch(void* const* d_in, const int* in_sizes, int n_in,
                              void* d_out, int out_size) {
    // Identify inputs by element count (robust to ordering):
    //   scale: 1 element, mul: 3600 elements, input_ids: B*T (largest)
    const float* scale = nullptr;
    const int*   ids   = nullptr;
    const int*   mul   = nullptr;
    for (int i = 0; i < n_in; i++) {
        if (in_sizes[i] == 1)               scale = (const float*)d_in[i];
        else if (in_sizes[i] == NN * NN)    mul   = (const int*)d_in[i];
        else                                ids   = (const int*)d_in[i];
    }
    a5_scan_kernel<<<BLOCKS, THREADS>>>(scale, ids, mul, (float*)d_out);
}

// round 15
// speedup vs baseline: 1.4048x; 1.3690x over previous
#include <cuda_runtime.h>
#include <cstdint>

#define BB 8192
#define TT 2048
#define NN 60
#define THREADS 64               // 2 warps per block
#define WARPS_PER_BLOCK (THREADS / 32)
#define BLOCKS (BB / WARPS_PER_BLOCK)   // 4096 blocks, one row per warp

// Math: mul is a group Cayley table, so the T-step scan
//   s_t = mul[x_t, s_{t-1}], s_0 = identity (0)
// collapses to the ordered product s = x_T * ... * x_1 (associativity only).
// The dataset's table is cyclic Z_60 (mul[a,b] = (a+b) % N): the ordered
// product is then (sum of x_t) % N — a pure memory-bound sum reduction.
//
// R14 = the measured-best R3 shape (one warp per row, 16 LDG.128 live in
// registers -> real MLP 16, DRAM ~62%) + PDL: the 1-block cyclic-check
// primary overlaps with the main kernel, whose warps issue all 16 loads
// BEFORE cudaGridDependencySynchronize(). The check + launch gap (the
// ~1.5-2us serial overhead in the 12.1us bench) hides under load latency.

__device__ int g_cyclic;

__global__ void check_cyclic_kernel(const int* __restrict__ mul) {
    int ok = 1;
    for (int i = threadIdx.x; i < NN * NN; i += blockDim.x) {
        int a = i / NN;
        int b = i - a * NN;
        ok &= (__ldg(&mul[i]) == (a + b) % NN);
    }
    ok = __syncthreads_and(ok);
    if (threadIdx.x == 0) g_cyclic = ok;
    cudaTriggerProgrammaticLaunchCompletion();
}

__global__ __launch_bounds__(THREADS)
void a5_scan_kernel(const float* __restrict__ scale_p,
                    const int*   __restrict__ ids,
                    const int*   __restrict__ mul,
                    float*       __restrict__ out) {
    const int lane = threadIdx.x & 31;
    const int row  = blockIdx.x * WARPS_PER_BLOCK + (threadIdx.x >> 5);
    if (row >= BB) return;

    // Issue the full 16-deep independent LDG.128 burst FIRST — needed by
    // both paths; keeps regs ~72 so ptxas cannot shrink the MLP window
    // (R3-proven), and overlaps with the PDL primary (cyclic check).
    const int4* rp = reinterpret_cast<const int4*>(ids + (size_t)row * TT);
    int4 v[16];
    #pragma unroll
    for (int i = 0; i < 16; i++)
        v[i] = rp[i * 32 + lane];

    const float scale = __ldg(scale_p);

    // Wait for the primary's g_cyclic to be visible (hidden under the
    // outstanding loads above).
    cudaGridDependencySynchronize();

    int s;
    if (g_cyclic) {
        int sum = 0;
        #pragma unroll
        for (int i = 0; i < 16; i++)
            sum += v[i].x + v[i].y + v[i].z + v[i].w;
        sum = __reduce_add_sync(0xffffffffu, sum);   // REDUX, no smem
        s = sum % NN;
    } else {
        // Generic ordered product over any group table (correctness path;
        // never taken on this dataset). Chunk c = i*32+lane covers times
        // [4c,4c+4), t0<t1<t2<t3: p = x3*x2*x1*x0 with a*b = mul[a][b].
        // Butterfly over 32 chunks (lane order = time order), then combine
        // the 16 group products later * earlier.
        int p[16];
        #pragma unroll
        for (int i = 0; i < 16; i++) {
            int a = __ldg(&mul[v[i].y * NN + v[i].x]);
            int b = __ldg(&mul[v[i].w * NN + v[i].z]);
            p[i] = __ldg(&mul[b * NN + a]);
        }
        #pragma unroll
        for (int i = 0; i < 16; i++) {
            int x = p[i];
            #pragma unroll
            for (int o = 1; o < 32; o <<= 1) {
                int other = __shfl_xor_sync(0xffffffffu, x, o);
                x = (lane & o) ? __ldg(&mul[x * NN + other])
                               : __ldg(&mul[other * NN + x]);
            }
            p[i] = x;
        }
        int acc = p[0];
        #pragma unroll
        for (int i = 1; i < 16; i++)
            acc = __ldg(&mul[p[i] * NN + acc]);
        s = acc;
    }

    const float hi = 10.0f * scale;
    const float lo = -10.0f * scale;

    // 60 outputs per row: lanes 0-31 write col lane; lanes 0-27 also write
    // col lane+32. Coalesced 240-byte row stores.
    float* op = out + (size_t)row * NN;
    op[lane] = (lane == s) ? hi : lo;
    if (lane < NN - 32)
        op[lane + 32] = (lane + 32 == s) ? hi : lo;
}

extern "C" void kernel_launch(void* const* d_in, const int* in_sizes, int n_in,
                              void* d_out, int out_size) {
    // Identify inputs by element count (robust to ordering):
    //   scale: 1 element, mul: 3600 elements, input_ids: B*T (largest)
    const float* scale = nullptr;
    const int*   ids   = nullptr;
    const int*   mul   = nullptr;
    for (int i = 0; i < n_in; i++) {
        if (in_sizes[i] == 1)               scale = (const float*)d_in[i];
        else if (in_sizes[i] == NN * NN)    mul   = (const int*)d_in[i];
        else                                ids   = (const int*)d_in[i];
    }

    // Primary: tiny cyclic-structure check.
    check_cyclic_kernel<<<1, 1024>>>(mul);

    // Secondary: main kernel with programmatic (PDL) dependency — launches
    // while the primary runs; warps sync on the flag only after their load
    // burst is in flight.
    cudaLaunchConfig_t cfg = {};
    cfg.gridDim  = dim3(BLOCKS, 1, 1);
    cfg.blockDim = dim3(THREADS, 1, 1);
    cfg.dynamicSmemBytes = 0;
    cfg.stream = 0;   // same (legacy default) stream as the primary
    cudaLaunchAttribute attr[1];
    attr[0].id = cudaLaunchAttributeProgrammaticStreamSerialization;
    attr[0].val.programmaticStreamSerializationAllowed = 1;
    cfg.attrs = attr;
    cfg.numAttrs = 1;
    cudaLaunchKernelEx(&cfg, a5_scan_kernel, scale, ids, mul, (float*)d_out);
}

// round 16
// speedup vs baseline: 1.4090x; 1.0030x over previous
#include <cuda_runtime.h>
#include <cstdint>

#define BB 8192
#define TT 2048
#define NN 60
#define THREADS 128              // 4 warps per block, one row per warp
#define WARPS_PER_BLOCK (THREADS / 32)
#define BLOCKS (BB / WARPS_PER_BLOCK)   // 2048 blocks

// Math: mul is a group Cayley table, so the T-step scan
//   s_t = mul[x_t, s_{t-1}], s_0 = identity (0)
// collapses to the ordered product s = x_T * ... * x_1 (associativity only).
// The dataset's table is cyclic Z_60 (mul[a,b] = (a+b) % N): the ordered
// product is then (sum of x_t) % N — a pure memory-bound sum reduction.
//
// Proven structure (R3/R15): one warp per row, 16 LDG.128 live in registers
// (regs~72 pins real MLP=16), PDL overlaps the 1-block cyclic-check primary
// with the main kernel's load burst. R16 micro-tune: 128-thread blocks
// (same 28 warps/SM, half the CTA scheduling events), streaming stores for
// the write-once output, dead guard removed.

__device__ int g_cyclic;

__global__ void check_cyclic_kernel(const int* __restrict__ mul) {
    int ok = 1;
    for (int i = threadIdx.x; i < NN * NN; i += blockDim.x) {
        int a = i / NN;
        int b = i - a * NN;
        ok &= (__ldg(&mul[i]) == (a + b) % NN);
    }
    ok = __syncthreads_and(ok);
    if (threadIdx.x == 0) g_cyclic = ok;
    cudaTriggerProgrammaticLaunchCompletion();
}

__global__ __launch_bounds__(THREADS)
void a5_scan_kernel(const float* __restrict__ scale_p,
                    const int*   __restrict__ ids,
                    const int*   __restrict__ mul,
                    float*       __restrict__ out) {
    const int lane = threadIdx.x & 31;
    const int row  = blockIdx.x * WARPS_PER_BLOCK + (threadIdx.x >> 5);

    // Issue the full 16-deep independent LDG.128 burst FIRST — needed by
    // both paths; keeps regs ~72 so ptxas cannot shrink the MLP window,
    // and overlaps with the PDL primary (cyclic check) + launch latency.
    const int4* rp = reinterpret_cast<const int4*>(ids + (size_t)row * TT);
    int4 v[16];
    #pragma unroll
    for (int i = 0; i < 16; i++)
        v[i] = rp[i * 32 + lane];

    const float scale = __ldg(scale_p);

    // Wait for the primary's g_cyclic (hidden under the outstanding loads).
    cudaGridDependencySynchronize();

    int s;
    if (g_cyclic) {
        int sum = 0;
        #pragma unroll
        for (int i = 0; i < 16; i++)
            sum += v[i].x + v[i].y + v[i].z + v[i].w;
        sum = __reduce_add_sync(0xffffffffu, sum);   // REDUX, no smem
        s = sum % NN;
    } else {
        // Generic ordered product over any group table (correctness path;
        // never taken on this dataset). Chunk c = i*32+lane covers times
        // [4c,4c+4), t0<t1<t2<t3: p = x3*x2*x1*x0 with a*b = mul[a][b].
        // Butterfly over 32 chunks (lane order = time order), then combine
        // the 16 group products later * earlier.
        int p[16];
        #pragma unroll
        for (int i = 0; i < 16; i++) {
            int a = __ldg(&mul[v[i].y * NN + v[i].x]);
            int b = __ldg(&mul[v[i].w * NN + v[i].z]);
            p[i] = __ldg(&mul[b * NN + a]);
        }
        #pragma unroll
        for (int i = 0; i < 16; i++) {
            int x = p[i];
            #pragma unroll
            for (int o = 1; o < 32; o <<= 1) {
                int other = __shfl_xor_sync(0xffffffffu, x, o);
                x = (lane & o) ? __ldg(&mul[x * NN + other])
                               : __ldg(&mul[other * NN + x]);
            }
            p[i] = x;
        }
        int acc = p[0];
        #pragma unroll
        for (int i = 1; i < 16; i++)
            acc = __ldg(&mul[p[i] * NN + acc]);
        s = acc;
    }

    const float hi = 10.0f * scale;
    const float lo = -10.0f * scale;

    // 60 outputs per row, write-once -> streaming stores (skip L2 alloc).
    float* op = out + (size_t)row * NN;
    __stcs(&op[lane], (lane == s) ? hi : lo);
    if (lane < NN - 32)
        __stcs(&op[lane + 32], (lane + 32 == s) ? hi : lo);
}

extern "C" void kernel_launch(void* const* d_in, const int* in_sizes, int n_in,
                              void* d_out, int out_size) {
    // Identify inputs by element count (robust to ordering):
    //   scale: 1 element, mul: 3600 elements, input_ids: B*T (largest)
    const float* scale = nullptr;
    const int*   ids   = nullptr;
    const int*   mul   = nullptr;
    for (int i = 0; i < n_in; i++) {
        if (in_sizes[i] == 1)               scale = (const float*)d_in[i];
        else if (in_sizes[i] == NN * NN)    mul   = (const int*)d_in[i];
        else                                ids   = (const int*)d_in[i];
    }

    // Primary: tiny cyclic-structure check.
    check_cyclic_kernel<<<1, 1024>>>(mul);

    // Secondary: main kernel with programmatic (PDL) dependency — launches
    // while the primary runs; warps sync on the flag only after their load
    // burst is in flight.
    cudaLaunchConfig_t cfg = {};
    cfg.gridDim  = dim3(BLOCKS, 1, 1);
    cfg.blockDim = dim3(THREADS, 1, 1);
    cfg.dynamicSmemBytes = 0;
    cfg.stream = 0;   // same (legacy default) stream as the primary
    cudaLaunchAttribute attr[1];
    attr[0].id = cudaLaunchAttributeProgrammaticStreamSerialization;
    attr[0].val.programmaticStreamSerializationAllowed = 1;
    cfg.attrs = attr;
    cfg.numAttrs = 1;
    cudaLaunchKernelEx(&cfg, a5_scan_kernel, scale, ids, mul, (float*)d_out);
}